// round 7
// baseline (speedup 1.0000x reference)
#include <cuda_runtime.h>
#include <cuda_bf16.h>
#include <cstdint>

// Problem constants
#define BB 4
#define LT 1024
#define LS 1024
#define DD 1024
#define HH 16
#define HD 64
#define FF 4096
#define MTOT (BB*LT)   // 4096 rows

#define SLOT (MTOT*DD)                     // 4M floats
#define WSZ  (DD*DD)                       // 1M floats
// scratch layout (floats):
//   [0..5)*SLOT   : bh, bq, battn, bx1, bx2
//   5*SLOT        : bffn (MTOT*FF)
//   WBASE + i*WSZ : 8 rounded+transposed D x D weights
//   WBASE + 8*WSZ : w1T (4*WSZ), +12*WSZ: w2T (4*WSZ), +16*WSZ: memr (4*WSZ)
#define WBASE ((size_t)5*SLOT + (size_t)MTOT*FF)
__device__ float g_scratch[WBASE + 20*(size_t)WSZ];

// ---------------------------------------------------------------------------
__device__ __forceinline__ uint32_t f2tf32(float f) {
    uint32_t u;
    asm("cvt.rna.tf32.f32 %0, %1;" : "=r"(u) : "f"(f));
    return u;
}
__device__ __forceinline__ float rtf(float f) {
    return __uint_as_float(f2tf32(f));
}

__device__ __forceinline__ void mma_tf32(float* d, const uint32_t* a, const uint32_t* b) {
    asm volatile(
        "mma.sync.aligned.m16n8k8.row.col.f32.tf32.tf32.f32 "
        "{%0,%1,%2,%3}, {%4,%5,%6,%7}, {%8,%9}, {%0,%1,%2,%3};"
        : "+f"(d[0]), "+f"(d[1]), "+f"(d[2]), "+f"(d[3])
        : "r"(a[0]), "r"(a[1]), "r"(a[2]), "r"(a[3]), "r"(b[0]), "r"(b[1]));
}

__device__ __forceinline__ void cp16(uint32_t dst, const float* src) {
    asm volatile("cp.async.cg.shared.global [%0], [%1], 16;" :: "r"(dst), "l"(src));
}

// ldmatrix x4 (b16): tf32 16-bit pairs move intact -> tf32 fragments.
__device__ __forceinline__ void ldsm4(uint32_t* r, uint32_t saddr) {
    asm volatile("ldmatrix.sync.aligned.m8n8.x4.shared.b16 {%0,%1,%2,%3}, [%4];"
        : "=r"(r[0]), "=r"(r[1]), "=r"(r[2]), "=r"(r[3]) : "r"(saddr));
}

// ---------------------------------------------------------------------------
// Preprocess: round to tf32 (elementwise)
__global__ void round_tf32_kernel(const float4* __restrict__ in,
                                  float4* __restrict__ out)
{
    int idx = blockIdx.x * 256 + threadIdx.x;
    float4 v = in[idx];
    v.x = rtf(v.x); v.y = rtf(v.y); v.z = rtf(v.z); v.w = rtf(v.w);
    out[idx] = v;
}

// Preprocess: round + transpose  in[K][N] -> out[N][K]
__global__ void xpose_tf32(const float* __restrict__ in, float* __restrict__ out,
                           int K, int N)
{
    __shared__ float t[32][33];
    int n0 = blockIdx.x * 32, k0 = blockIdx.y * 32;
    int tx = threadIdx.x, ty = threadIdx.y;   // 32 x 8
    #pragma unroll
    for (int i = 0; i < 4; i++)
        t[ty + i * 8][tx] = in[(size_t)(k0 + ty + i * 8) * N + n0 + tx];
    __syncthreads();
    #pragma unroll
    for (int i = 0; i < 4; i++)
        out[(size_t)(n0 + ty + i * 8) * K + k0 + tx] = rtf(t[tx][ty + i * 8]);
}

// ---------------------------------------------------------------------------
// RMSNorm (output rounded to tf32)
__global__ void rmsnorm_kernel(const float* __restrict__ x,
                               const float* __restrict__ g,
                               float* __restrict__ out)
{
    __shared__ float red[256];
    int row = blockIdx.x;
    int tid = threadIdx.x;
    const float4* xr = (const float4*)(x + (size_t)row * DD);
    float4 v = xr[tid];
    float ss = v.x*v.x + v.y*v.y + v.z*v.z + v.w*v.w;
    red[tid] = ss;
    __syncthreads();
    #pragma unroll
    for (int s = 128; s > 0; s >>= 1) {
        if (tid < s) red[tid] += red[tid + s];
        __syncthreads();
    }
    float inv = rsqrtf(red[0] * (1.0f/(float)DD) + 1e-6f);
    const float4 gg = ((const float4*)g)[tid];
    float4 o;
    o.x = rtf(v.x * inv * gg.x);
    o.y = rtf(v.y * inv * gg.y);
    o.z = rtf(v.z * inv * gg.z);
    o.w = rtf(v.w * inv * gg.w);
    ((float4*)(out + (size_t)row * DD))[tid] = o;
}

// ---------------------------------------------------------------------------
// TF32 tensor-core GEMM with LDSM fragment loads.
// C[M,N] = A[M,K] @ BT[N,K]^T. Both operands pre-rounded to tf32.
// Epilogues: 1 KV-transpose(+round), 2 resid, 3 relu+round, 4 plain+round.
#define TC_BM 128
#define TC_BN 128
#define TC_BK 32
#define TCS 36                             // smem tile stride (conflict-free LDSM)
#define TILE_ELEMS (128 * TCS)             // 4608 floats
#define TC_SMEM_BYTES (4 * TILE_ELEMS * 4) // 73728

template<int EPI>
__global__ __launch_bounds__(256)
void tc_gemm(const float* __restrict__ A, const float* __restrict__ BT,
             float* __restrict__ C, const float* __restrict__ R,
             int M, int N, int K)
{
    extern __shared__ float sm[];
    const uint32_t smb = (uint32_t)__cvta_generic_to_shared(sm);
    const uint32_t asm0 = smb;
    const uint32_t asm1 = smb + TILE_ELEMS * 4;
    const uint32_t bsm0 = smb + 2 * TILE_ELEMS * 4;
    const uint32_t bsm1 = smb + 3 * TILE_ELEMS * 4;

    const int tid  = threadIdx.x;
    const int wid  = tid >> 5;
    const int lane = tid & 31;
    const int g    = lane >> 2;
    const int t    = lane & 3;
    const int wm   = wid & 1;
    const int wn   = wid >> 1;
    const int m0   = blockIdx.y * TC_BM;
    const int n0   = blockIdx.x * TC_BN;

    const int fr = (lane & 7) + ((lane >> 3) & 1) * 8;   // A-pattern row
    const int fk = ((lane >> 4) & 1) * 4;                // A-pattern k
    const int br = (lane & 7) + ((lane >> 4) & 1) * 8;   // B-pattern row
    const int bk = ((lane >> 3) & 1) * 4;                // B-pattern k

    const float* Ab = A  + (size_t)m0 * K;
    const float* Bb = BT + (size_t)n0 * K;

    float acc[4][4][4];
    #pragma unroll
    for (int mi = 0; mi < 4; mi++)
        #pragma unroll
        for (int ni = 0; ni < 4; ni++)
            #pragma unroll
            for (int r = 0; r < 4; r++) acc[mi][ni][r] = 0.0f;

    const int NT = K / TC_BK;

    #define G_LOAD(abuf, bbuf, kk0)                                           \
        _Pragma("unroll")                                                     \
        for (int p_ = 0; p_ < 4; p_++) {                                      \
            int idx_ = tid + p_ * 256;                                        \
            int r_ = idx_ >> 3, c_ = (idx_ & 7) * 4;                          \
            cp16((abuf) + (uint32_t)((r_ * TCS + c_) << 2),                   \
                 Ab + (size_t)r_ * K + (kk0) + c_);                           \
            cp16((bbuf) + (uint32_t)((r_ * TCS + c_) << 2),                   \
                 Bb + (size_t)r_ * K + (kk0) + c_);                           \
        }

    G_LOAD(asm0, bsm0, 0);
    asm volatile("cp.async.commit_group;");

    for (int kt = 0; kt < NT; kt++) {
        const int cur = kt & 1;
        if (kt + 1 < NT) {
            const int k0 = (kt + 1) * TC_BK;
            G_LOAD(cur ? asm0 : asm1, cur ? bsm0 : bsm1, k0);
            asm volatile("cp.async.commit_group;");
            asm volatile("cp.async.wait_group 1;");
        } else {
            asm volatile("cp.async.wait_group 0;");
        }
        __syncthreads();

        const uint32_t aaddr = (cur ? asm1 : asm0)
                             + (uint32_t)(((wm * 64 + fr) * TCS + fk) << 2);
        const uint32_t baddr = (cur ? bsm1 : bsm0)
                             + (uint32_t)(((wn * 32 + br) * TCS + bk) << 2);

        #pragma unroll
        for (int kk = 0; kk < 4; kk++) {
            uint32_t af[4][4];
            uint32_t bfr[2][4];
            #pragma unroll
            for (int mi = 0; mi < 4; mi++)
                ldsm4(af[mi], aaddr + (uint32_t)(((mi * 16 * TCS) + kk * 8) << 2));
            #pragma unroll
            for (int p = 0; p < 2; p++)
                ldsm4(bfr[p], baddr + (uint32_t)(((p * 16 * TCS) + kk * 8) << 2));
            #pragma unroll
            for (int mi = 0; mi < 4; mi++)
                #pragma unroll
                for (int p = 0; p < 2; p++) {
                    mma_tf32(acc[mi][2 * p],     af[mi], &bfr[p][0]);
                    mma_tf32(acc[mi][2 * p + 1], af[mi], &bfr[p][2]);
                }
        }
        __syncthreads();
    }
    #undef G_LOAD

    const int mbase = m0 + wm * 64 + g;
    const int nbase = n0 + wn * 32 + 2 * t;

    if (EPI == 1) {
        #pragma unroll
        for (int mi = 0; mi < 4; mi++) {
            #pragma unroll
            for (int ni = 0; ni < 4; ni++) {
                #pragma unroll
                for (int half = 0; half < 2; half++) {
                    int m = mbase + mi * 16 + half * 8;
                    int b = m >> 10, l = m & 1023;
                    #pragma unroll
                    for (int c = 0; c < 2; c++) {
                        int n = nbase + ni * 8 + c;
                        int h = n >> 6, d = n & 63;
                        C[(((size_t)(b * HH + h) * LT + l) << 6) + d] =
                            rtf(acc[mi][ni][half * 2 + c]);
                    }
                }
            }
        }
    } else {
        #pragma unroll
        for (int mi = 0; mi < 4; mi++) {
            #pragma unroll
            for (int ni = 0; ni < 4; ni++) {
                int n = nbase + ni * 8;
                #pragma unroll
                for (int half = 0; half < 2; half++) {
                    int m = mbase + mi * 16 + half * 8;
                    size_t off = (size_t)m * N + n;
                    float2 v = make_float2(acc[mi][ni][half * 2], acc[mi][ni][half * 2 + 1]);
                    if (EPI == 2) {
                        float2 r = *(const float2*)(R + off);
                        v.x += r.x; v.y += r.y;
                    }
                    if (EPI == 3) {
                        v.x = rtf(fmaxf(v.x, 0.f)); v.y = rtf(fmaxf(v.y, 0.f));
                    }
                    if (EPI == 4) {
                        v.x = rtf(v.x); v.y = rtf(v.y);
                    }
                    *(float2*)(C + off) = v;
                }
            }
        }
    }
}

// ---------------------------------------------------------------------------
// Tensor-core flash attention (tf32 mma + LDSM, online softmax).
// Q/K/V all pre-rounded tf32 (raw-bit fragment loads).
#define ATT_SMEM0 (26624 * 4)
#define ATT_SMEM1 (35328 * 4)

#define LOAD_TILE(dstoff, srcptr, srcstride, STRIDE)                          \
    _Pragma("unroll")                                                         \
    for (int i_ = 0; i_ < 8; i_++) {                                          \
        int idx_ = tid + i_ * 128;                                            \
        int r_ = idx_ >> 4, c_ = (idx_ & 15) * 4;                             \
        cp16(sbase + (uint32_t)(((dstoff) + r_ * (STRIDE) + c_) << 2),        \
             (srcptr) + (size_t)r_ * (srcstride) + c_);                       \
    }

template<int MODE>
__global__ __launch_bounds__(128)
void attn_tc(const float* __restrict__ Q, const float* __restrict__ K,
             const float* __restrict__ V, const float* __restrict__ bias,
             float* __restrict__ O)
{
    extern __shared__ float smf[];
    const int tid  = threadIdx.x;
    const int wid  = tid >> 5;
    const int lane = tid & 31;
    const int g    = lane >> 2;
    const int t    = lane & 3;
    const int qt   = blockIdx.x;
    const int h    = blockIdx.y;
    const int b    = blockIdx.z;

    const uint32_t sbase = (uint32_t)__cvta_generic_to_shared(smf);

    const int fr = (lane & 7) + ((lane >> 3) & 1) * 8;
    const int fk = ((lane >> 4) & 1) * 4;
    const int br = (lane & 7) + ((lane >> 4) & 1) * 8;
    const int bk = ((lane >> 3) & 1) * 4;

    const float* Qg = Q + ((size_t)(b * LT) + qt * 64) * DD + h * HD;
    const float* Kg = K + ((size_t)(b * HH + h)) * LS * HD;
    const float* Vg = V + ((size_t)(b * HH + h)) * LS * HD;
    const float* Bg = (MODE == 1) ? bias + ((size_t)h * LT + qt * 64) * LS : nullptr;

    {
        LOAD_TILE(0,     Qg, DD, 68);
        LOAD_TILE(4352,  Kg, HD, 68);
        LOAD_TILE(13056, Vg, HD, 72);
        if (MODE == 1) {
            LOAD_TILE(26624, Bg, LS, 68);
        }
        asm volatile("cp.async.commit_group;");
    }

    float oacc[8][4];
    #pragma unroll
    for (int ni = 0; ni < 8; ni++)
        #pragma unroll
        for (int r = 0; r < 4; r++) oacc[ni][r] = 0.0f;

    float mrow[2] = { -1e30f, -1e30f };
    float lrow[2] = { 0.0f, 0.0f };

    const int ktmax = (MODE == 0) ? qt : (LS / 64 - 1);

    const uint32_t qaddr = sbase + (uint32_t)((((wid * 16 + fr) * 68) + fk) << 2);
    const uint32_t paddr = sbase + (uint32_t)(((22272 + (wid * 16 + fr) * 68) + fk) << 2);

    for (int kt = 0; kt <= ktmax; kt++) {
        const int cur = kt & 1;
        __syncthreads();
        if (kt + 1 <= ktmax) {
            const int nk = kt + 1;
            const uint32_t koff = (cur == 0) ? 8704u  : 4352u;
            const uint32_t voff = (cur == 0) ? 17664u : 13056u;
            const float* kp = Kg + (size_t)nk * 64 * HD;
            const float* vp = Vg + (size_t)nk * 64 * HD;
            LOAD_TILE(koff, kp, HD, 68);
            LOAD_TILE(voff, vp, HD, 72);
            if (MODE == 1) {
                const uint32_t boff = (cur == 0) ? 30976u : 26624u;
                const float* bp = Bg + (size_t)nk * 64;
                LOAD_TILE(boff, bp, LS, 68);
            }
            asm volatile("cp.async.commit_group;");
            asm volatile("cp.async.wait_group 1;");
        } else {
            asm volatile("cp.async.wait_group 0;");
        }
        __syncthreads();

        const uint32_t kaddr = sbase + (uint32_t)((((cur ? 8704 : 4352) + br * 68) + bk) << 2);
        const float*   Vsc   = smf + (cur ? 17664 : 13056);
        const float*   Bic   = smf + (cur ? 30976 : 26624);

        // ---- S = Q K^T ----
        float sacc[8][4];
        #pragma unroll
        for (int ni = 0; ni < 8; ni++)
            #pragma unroll
            for (int r = 0; r < 4; r++) sacc[ni][r] = 0.0f;

        #pragma unroll
        for (int kk = 0; kk < 8; kk++) {
            uint32_t a[4];
            ldsm4(a, qaddr + (uint32_t)((kk * 8) << 2));
            #pragma unroll
            for (int p = 0; p < 4; p++) {
                uint32_t bb[4];
                ldsm4(bb, kaddr + (uint32_t)(((p * 16 * 68) + kk * 8) << 2));
                mma_tf32(sacc[2 * p],     a, &bb[0]);
                mma_tf32(sacc[2 * p + 1], a, &bb[2]);
            }
        }

        // ---- softmax ----
        uint32_t* Psu = (uint32_t*)(smf + 22272);
        #pragma unroll
        for (int half = 0; half < 2; half++) {
            const int row_l = wid * 16 + g + half * 8;
            float mx = -1e30f;
            #pragma unroll
            for (int ni = 0; ni < 8; ni++) {
                #pragma unroll
                for (int c = 0; c < 2; c++) {
                    float v = sacc[ni][half * 2 + c] * 0.125f;
                    if (MODE == 0) {
                        if (kt == qt) {
                            int keyl = ni * 8 + 2 * t + c;
                            if (keyl > row_l) v = -1e30f;
                        }
                    } else {
                        v += Bic[row_l * 68 + ni * 8 + 2 * t + c];
                    }
                    sacc[ni][half * 2 + c] = v;
                    mx = fmaxf(mx, v);
                }
            }
            mx = fmaxf(mx, __shfl_xor_sync(0xffffffffu, mx, 1));
            mx = fmaxf(mx, __shfl_xor_sync(0xffffffffu, mx, 2));
            float mnew = fmaxf(mrow[half], mx);
            float corr = __expf(mrow[half] - mnew);
            mrow[half] = mnew;
            float sum = 0.0f;
            #pragma unroll
            for (int ni = 0; ni < 8; ni++) {
                float p0 = __expf(sacc[ni][half * 2]     - mnew);
                float p1 = __expf(sacc[ni][half * 2 + 1] - mnew);
                sum += p0 + p1;
                sacc[ni][half * 2]     = p0;
                sacc[ni][half * 2 + 1] = p1;
            }
            sum += __shfl_xor_sync(0xffffffffu, sum, 1);
            sum += __shfl_xor_sync(0xffffffffu, sum, 2);
            lrow[half] = lrow[half] * corr + sum;
            #pragma unroll
            for (int ni = 0; ni < 8; ni++) {
                oacc[ni][half * 2]     *= corr;
                oacc[ni][half * 2 + 1] *= corr;
                uint2 pp = make_uint2(f2tf32(sacc[ni][half * 2]),
                                      f2tf32(sacc[ni][half * 2 + 1]));
                *(uint2*)&Psu[row_l * 68 + ni * 8 + 2 * t] = pp;
            }
        }
        __syncwarp();

        // ---- O += P V ----
        {
            const uint32_t* vbu = (const uint32_t*)(Vsc + t * 72 + g);
            #pragma unroll
            for (int kk = 0; kk < 8; kk++) {
                uint32_t a[4];
                ldsm4(a, paddr + (uint32_t)((kk * 8) << 2));
                #pragma unroll
                for (int ni = 0; ni < 8; ni++) {
                    uint32_t bf[2];
                    bf[0] = vbu[kk * 8 * 72 + ni * 8];
                    bf[1] = vbu[kk * 8 * 72 + 4 * 72 + ni * 8];
                    mma_tf32(oacc[ni], a, bf);
                }
            }
        }
        __syncwarp();
    }

    // ---- normalize + write O (rounded: feeds GEMM A) ----
    #pragma unroll
    for (int half = 0; half < 2; half++) {
        const int row_l = wid * 16 + g + half * 8;
        const int qg = qt * 64 + row_l;
        const float invl = 1.0f / lrow[half];
        float* op = O + ((size_t)(b * LT) + qg) * DD + h * HD;
        #pragma unroll
        for (int ni = 0; ni < 8; ni++) {
            float2 v = make_float2(rtf(oacc[ni][half * 2] * invl),
                                   rtf(oacc[ni][half * 2 + 1] * invl));
            *(float2*)(op + ni * 8 + 2 * t) = v;
        }
    }
}

// ---------------------------------------------------------------------------
extern "C" void kernel_launch(void* const* d_in, const int* in_sizes, int n_in,
                              void* d_out, int out_size)
{
    const float* x        = (const float*)d_in[0];
    const float* memory   = (const float*)d_in[1];
    const float* pos_emb  = (const float*)d_in[2];
    const float* gamma_sa = (const float*)d_in[4];
    const float* wq_s     = (const float*)d_in[5];
    const float* wk_s     = (const float*)d_in[6];
    const float* wv_s     = (const float*)d_in[7];
    const float* wo_s     = (const float*)d_in[8];
    const float* gamma_ca = (const float*)d_in[9];
    const float* wq_c     = (const float*)d_in[10];
    const float* wk_c     = (const float*)d_in[11];
    const float* wv_c     = (const float*)d_in[12];
    const float* wo_c     = (const float*)d_in[13];
    const float* gamma_m  = (const float*)d_in[14];
    const float* w1       = (const float*)d_in[15];
    const float* w2       = (const float*)d_in[16];

    float* scratch = nullptr;
    cudaGetSymbolAddress((void**)&scratch, g_scratch);
    float* bh    = scratch;
    float* bq    = scratch + (size_t)1 * SLOT;
    float* battn = scratch + (size_t)2 * SLOT;
    float* bx1   = scratch + (size_t)3 * SLOT;
    float* bx2   = scratch + (size_t)4 * SLOT;
    float* bffn  = scratch + (size_t)5 * SLOT;
    float* wbase = scratch + WBASE;
    float* twq_s = wbase + 0 * (size_t)WSZ;
    float* twk_s = wbase + 1 * (size_t)WSZ;
    float* twv_s = wbase + 2 * (size_t)WSZ;
    float* two_s = wbase + 3 * (size_t)WSZ;
    float* twq_c = wbase + 4 * (size_t)WSZ;
    float* twk_c = wbase + 5 * (size_t)WSZ;
    float* twv_c = wbase + 6 * (size_t)WSZ;
    float* two_c = wbase + 7 * (size_t)WSZ;
    float* tw1   = wbase + 8 * (size_t)WSZ;    // [F][D]
    float* tw2   = wbase + 12 * (size_t)WSZ;   // [D][F]
    float* rmem  = wbase + 16 * (size_t)WSZ;

    float* out   = (float*)d_out;
    float* o_mlp = out;
    float* o_ks  = out + (size_t)1 * SLOT;
    float* o_vs  = out + (size_t)2 * SLOT;
    float* o_kc  = out + (size_t)3 * SLOT;
    float* o_vc  = out + (size_t)4 * SLOT;

    cudaFuncSetAttribute(tc_gemm<1>, cudaFuncAttributeMaxDynamicSharedMemorySize, TC_SMEM_BYTES);
    cudaFuncSetAttribute(tc_gemm<2>, cudaFuncAttributeMaxDynamicSharedMemorySize, TC_SMEM_BYTES);
    cudaFuncSetAttribute(tc_gemm<3>, cudaFuncAttributeMaxDynamicSharedMemorySize, TC_SMEM_BYTES);
    cudaFuncSetAttribute(tc_gemm<4>, cudaFuncAttributeMaxDynamicSharedMemorySize, TC_SMEM_BYTES);
    cudaFuncSetAttribute(attn_tc<0>, cudaFuncAttributeMaxDynamicSharedMemorySize, ATT_SMEM0);
    cudaFuncSetAttribute(attn_tc<1>, cudaFuncAttributeMaxDynamicSharedMemorySize, ATT_SMEM1);

    // ---- preprocess: round+transpose weights, round memory ----
    const dim3 xb(32, 8);
    xpose_tf32<<<dim3(DD/32, DD/32), xb>>>(wq_s, twq_s, DD, DD);
    xpose_tf32<<<dim3(DD/32, DD/32), xb>>>(wk_s, twk_s, DD, DD);
    xpose_tf32<<<dim3(DD/32, DD/32), xb>>>(wv_s, twv_s, DD, DD);
    xpose_tf32<<<dim3(DD/32, DD/32), xb>>>(wo_s, two_s, DD, DD);
    xpose_tf32<<<dim3(DD/32, DD/32), xb>>>(wq_c, twq_c, DD, DD);
    xpose_tf32<<<dim3(DD/32, DD/32), xb>>>(wk_c, twk_c, DD, DD);
    xpose_tf32<<<dim3(DD/32, DD/32), xb>>>(wv_c, twv_c, DD, DD);
    xpose_tf32<<<dim3(DD/32, DD/32), xb>>>(wo_c, two_c, DD, DD);
    xpose_tf32<<<dim3(FF/32, DD/32), xb>>>(w1, tw1, DD, FF);
    xpose_tf32<<<dim3(DD/32, FF/32), xb>>>(w2, tw2, FF, DD);
    round_tf32_kernel<<<(4*WSZ)/4/256, 256>>>((const float4*)memory, (float4*)rmem);

    const dim3 gD(DD / TC_BN, MTOT / TC_BM);   // (8, 32)
    const dim3 gF(FF / TC_BN, MTOT / TC_BM);   // (32, 32)
    const dim3 gA(LT / 64, HH, BB);

    // ---- self-attention block ----
    rmsnorm_kernel<<<MTOT, 256>>>(x, gamma_sa, bh);
    tc_gemm<4><<<gD, 256, TC_SMEM_BYTES>>>(bh, twq_s, bq,   nullptr, MTOT, DD, DD);
    tc_gemm<1><<<gD, 256, TC_SMEM_BYTES>>>(bh, twk_s, o_ks, nullptr, MTOT, DD, DD);
    tc_gemm<1><<<gD, 256, TC_SMEM_BYTES>>>(bh, twv_s, o_vs, nullptr, MTOT, DD, DD);
    attn_tc<0><<<gA, 128, ATT_SMEM0>>>(bq, o_ks, o_vs, nullptr, battn);
    tc_gemm<2><<<gD, 256, TC_SMEM_BYTES>>>(battn, two_s, bx1, x, MTOT, DD, DD);

    // ---- cross-attention block ----
    rmsnorm_kernel<<<MTOT, 256>>>(bx1, gamma_ca, bh);
    tc_gemm<4><<<gD, 256, TC_SMEM_BYTES>>>(bh,   twq_c, bq,   nullptr, MTOT, DD, DD);
    tc_gemm<1><<<gD, 256, TC_SMEM_BYTES>>>(rmem, twk_c, o_kc, nullptr, MTOT, DD, DD);
    tc_gemm<1><<<gD, 256, TC_SMEM_BYTES>>>(rmem, twv_c, o_vc, nullptr, MTOT, DD, DD);
    attn_tc<1><<<gA, 128, ATT_SMEM1>>>(bq, o_kc, o_vc, pos_emb, battn);
    tc_gemm<2><<<gD, 256, TC_SMEM_BYTES>>>(battn, two_c, bx2, bx1, MTOT, DD, DD);

    // ---- FFN block ----
    rmsnorm_kernel<<<MTOT, 256>>>(bx2, gamma_m, bh);
    tc_gemm<3><<<gF, 256, TC_SMEM_BYTES>>>(bh,   tw1, bffn,  nullptr, MTOT, FF, DD);
    tc_gemm<2><<<gD, 256, TC_SMEM_BYTES>>>(bffn, tw2, o_mlp, bx2,     MTOT, DD, FF);
}

// round 8
// speedup vs baseline: 1.4384x; 1.4384x over previous
#include <cuda_runtime.h>
#include <cuda_bf16.h>
#include <cstdint>

// Problem constants
#define BB 4
#define LT 1024
#define LS 1024
#define DD 1024
#define HH 16
#define HD 64
#define FF 4096
#define MTOT (BB*LT)   // 4096 rows

#define SLOT (MTOT*DD)                     // 4M floats
#define WSZ  (DD*DD)                       // 1M floats
// scratch: 5 act slots + ffn + rounded weights/memory
#define WBASE ((size_t)5*SLOT + (size_t)MTOT*FF)
__device__ float g_scratch[WBASE + 20*(size_t)WSZ];

// ---------------------------------------------------------------------------
__device__ __forceinline__ uint32_t f2tf32(float f) {
    uint32_t u;
    asm("cvt.rna.tf32.f32 %0, %1;" : "=r"(u) : "f"(f));
    return u;
}
__device__ __forceinline__ float rtf(float f) {   // round to tf32, as float
    return __uint_as_float(f2tf32(f));
}

__device__ __forceinline__ void mma_tf32(float* d, const uint32_t* a, const uint32_t* b) {
    asm volatile(
        "mma.sync.aligned.m16n8k8.row.col.f32.tf32.tf32.f32 "
        "{%0,%1,%2,%3}, {%4,%5,%6,%7}, {%8,%9}, {%0,%1,%2,%3};"
        : "+f"(d[0]), "+f"(d[1]), "+f"(d[2]), "+f"(d[3])
        : "r"(a[0]), "r"(a[1]), "r"(a[2]), "r"(a[3]), "r"(b[0]), "r"(b[1]));
}

__device__ __forceinline__ void cp16(uint32_t dst, const float* src) {
    asm volatile("cp.async.cg.shared.global [%0], [%1], 16;" :: "r"(dst), "l"(src));
}

// ---------------------------------------------------------------------------
// Elementwise tf32 rounding pass (float4 per thread)
__global__ void round_tf32_kernel(const float4* __restrict__ in,
                                  float4* __restrict__ out)
{
    int idx = blockIdx.x * 256 + threadIdx.x;
    float4 v = in[idx];
    v.x = rtf(v.x); v.y = rtf(v.y); v.z = rtf(v.z); v.w = rtf(v.w);
    out[idx] = v;
}

// ---------------------------------------------------------------------------
// RMSNorm (output rounded to tf32 — it only feeds GEMM A operands)
__global__ void rmsnorm_kernel(const float* __restrict__ x,
                               const float* __restrict__ g,
                               float* __restrict__ out)
{
    __shared__ float red[256];
    int row = blockIdx.x;
    int tid = threadIdx.x;
    const float4* xr = (const float4*)(x + (size_t)row * DD);
    float4 v = xr[tid];
    float ss = v.x*v.x + v.y*v.y + v.z*v.z + v.w*v.w;
    red[tid] = ss;
    __syncthreads();
    #pragma unroll
    for (int s = 128; s > 0; s >>= 1) {
        if (tid < s) red[tid] += red[tid + s];
        __syncthreads();
    }
    float inv = rsqrtf(red[0] * (1.0f/(float)DD) + 1e-6f);
    const float4 gg = ((const float4*)g)[tid];
    float4 o;
    o.x = rtf(v.x * inv * gg.x);
    o.y = rtf(v.y * inv * gg.y);
    o.z = rtf(v.z * inv * gg.z);
    o.w = rtf(v.w * inv * gg.w);
    ((float4*)(out + (size_t)row * DD))[tid] = o;
}

// ---------------------------------------------------------------------------
// TF32 tensor-core GEMM, 4-stage cp.async pipeline, BK=16, one sync/iter.
// C[M,N] = A[M,K] @ B[K,N]. Operands pre-rounded to tf32 (raw-bit LDS).
// Epilogues: 1 KV-transpose, 2 resid, 3 relu+round, 4 plain+round.
#define TC_BM 128
#define TC_BN 128
#define TC_BK 16
#define AS_STRIDE 28                        // 28g+t mod 32 bijective -> conflict-free
#define BS_STRIDE (TC_BN + 8)               // 136, proven conflict-free
#define A_STAGE (TC_BM * AS_STRIDE)         // 3584 floats
#define B_STAGE (TC_BK * BS_STRIDE)         // 2176 floats
#define STAGE_ELEMS (A_STAGE + B_STAGE)     // 5760 floats
#define TC_SMEM_BYTES (4 * STAGE_ELEMS * 4) // 92160 B

template<int EPI>
__global__ __launch_bounds__(256)
void tc_gemm(const float* __restrict__ A, const float* __restrict__ B,
             float* __restrict__ C, const float* __restrict__ R,
             int M, int N, int K)
{
    extern __shared__ float sm[];
    const uint32_t smb = (uint32_t)__cvta_generic_to_shared(sm);

    const int tid  = threadIdx.x;
    const int wid  = tid >> 5;
    const int lane = tid & 31;
    const int g    = lane >> 2;
    const int t    = lane & 3;
    const int wm   = wid & 1;
    const int wn   = wid >> 1;
    const int m0   = blockIdx.y * TC_BM;
    const int n0   = blockIdx.x * TC_BN;

    const float* Ag = A + (size_t)m0 * K;
    const float* Bg = B + n0;

    float acc[4][4][4];
    #pragma unroll
    for (int mi = 0; mi < 4; mi++)
        #pragma unroll
        for (int ni = 0; ni < 4; ni++)
            #pragma unroll
            for (int r = 0; r < 4; r++) acc[mi][ni][r] = 0.0f;

    const int NT = K / TC_BK;

    // per-stage loader: 512 A-chunks + 512 B-chunks, 2+2 per thread
    #define G_LOAD(s, k0)                                                     \
    {                                                                         \
        uint32_t ab_ = smb + (uint32_t)((s) * STAGE_ELEMS * 4);               \
        uint32_t bb_ = ab_ + (uint32_t)(A_STAGE * 4);                         \
        _Pragma("unroll")                                                     \
        for (int i_ = 0; i_ < 2; i_++) {                                      \
            int idx_ = tid + i_ * 256;                                        \
            int ar_ = idx_ >> 2, ac_ = (idx_ & 3) * 4;                        \
            cp16(ab_ + (uint32_t)((ar_ * AS_STRIDE + ac_) << 2),              \
                 Ag + (size_t)ar_ * K + (k0) + ac_);                          \
            int br_ = idx_ >> 5, bc_ = (idx_ & 31) * 4;                       \
            cp16(bb_ + (uint32_t)((br_ * BS_STRIDE + bc_) << 2),              \
                 Bg + (size_t)((k0) + br_) * N + bc_);                        \
        }                                                                     \
    }

    // prologue: stages 0,1 in flight
    G_LOAD(0, 0);
    asm volatile("cp.async.commit_group;");
    G_LOAD(1, TC_BK);
    asm volatile("cp.async.commit_group;");

    for (int kt = 0; kt < NT; kt++) {
        if (kt + 2 < NT) {
            G_LOAD((kt + 2) & 3, (kt + 2) * TC_BK);
        }
        asm volatile("cp.async.commit_group;");
        asm volatile("cp.async.wait_group 2;");
        __syncthreads();

        const float* As = sm + (kt & 3) * STAGE_ELEMS;
        const float* Bs = As + A_STAGE;
        const uint32_t* Ab = (const uint32_t*)(As + (wm * 64 + g) * AS_STRIDE + t);
        const uint32_t* Bb = (const uint32_t*)(Bs + t * BS_STRIDE + wn * 32 + g);

        #pragma unroll
        for (int kk = 0; kk < 2; kk++) {
            uint32_t af[4][4];
            uint32_t bf[4][2];
            #pragma unroll
            for (int mi = 0; mi < 4; mi++) {
                const uint32_t* p = Ab + mi * 16 * AS_STRIDE + kk * 8;
                af[mi][0] = p[0];
                af[mi][1] = p[8 * AS_STRIDE];
                af[mi][2] = p[4];
                af[mi][3] = p[8 * AS_STRIDE + 4];
            }
            #pragma unroll
            for (int ni = 0; ni < 4; ni++) {
                const uint32_t* p = Bb + kk * 8 * BS_STRIDE + ni * 8;
                bf[ni][0] = p[0];
                bf[ni][1] = p[4 * BS_STRIDE];
            }
            #pragma unroll
            for (int mi = 0; mi < 4; mi++)
                #pragma unroll
                for (int ni = 0; ni < 4; ni++)
                    mma_tf32(acc[mi][ni], af[mi], bf[ni]);
        }
    }
    #undef G_LOAD

    const int mbase = m0 + wm * 64 + g;
    const int nbase = n0 + wn * 32 + 2 * t;

    if (EPI == 1) {
        #pragma unroll
        for (int mi = 0; mi < 4; mi++) {
            #pragma unroll
            for (int ni = 0; ni < 4; ni++) {
                #pragma unroll
                for (int half = 0; half < 2; half++) {
                    int m = mbase + mi * 16 + half * 8;
                    int b = m >> 10, l = m & 1023;
                    #pragma unroll
                    for (int c = 0; c < 2; c++) {
                        int n = nbase + ni * 8 + c;
                        int h = n >> 6, d = n & 63;
                        C[(((size_t)(b * HH + h) * LT + l) << 6) + d] =
                            acc[mi][ni][half * 2 + c];
                    }
                }
            }
        }
    } else {
        #pragma unroll
        for (int mi = 0; mi < 4; mi++) {
            #pragma unroll
            for (int ni = 0; ni < 4; ni++) {
                int n = nbase + ni * 8;
                #pragma unroll
                for (int half = 0; half < 2; half++) {
                    int m = mbase + mi * 16 + half * 8;
                    size_t off = (size_t)m * N + n;
                    float2 v = make_float2(acc[mi][ni][half * 2], acc[mi][ni][half * 2 + 1]);
                    if (EPI == 2) {
                        float2 r = *(const float2*)(R + off);
                        v.x += r.x; v.y += r.y;
                    }
                    if (EPI == 3) {
                        v.x = rtf(fmaxf(v.x, 0.f)); v.y = rtf(fmaxf(v.y, 0.f));
                    }
                    if (EPI == 4) {
                        v.x = rtf(v.x); v.y = rtf(v.y);
                    }
                    *(float2*)(C + off) = v;
                }
            }
        }
    }
}

// ---------------------------------------------------------------------------
// Tensor-core flash attention (tf32 mma, online softmax) — R6 proven version.
// Q pre-rounded to tf32 (raw loads); K/V exact fp32 (cvt at frag load).
#define ATT_SMEM0 (26624 * 4)
#define ATT_SMEM1 (35328 * 4)

#define LOAD_TILE(dstoff, srcptr, srcstride, STRIDE)                          \
    _Pragma("unroll")                                                         \
    for (int i_ = 0; i_ < 8; i_++) {                                          \
        int idx_ = tid + i_ * 128;                                            \
        int r_ = idx_ >> 4, c_ = (idx_ & 15) * 4;                             \
        cp16(sbase + (uint32_t)(((dstoff) + r_ * (STRIDE) + c_) << 2),        \
             (srcptr) + (size_t)r_ * (srcstride) + c_);                       \
    }

template<int MODE>
__global__ __launch_bounds__(128)
void attn_tc(const float* __restrict__ Q, const float* __restrict__ K,
             const float* __restrict__ V, const float* __restrict__ bias,
             float* __restrict__ O)
{
    extern __shared__ float smf[];
    const int tid  = threadIdx.x;
    const int wid  = tid >> 5;
    const int lane = tid & 31;
    const int g    = lane >> 2;
    const int t    = lane & 3;
    const int qt   = blockIdx.x;
    const int h    = blockIdx.y;
    const int b    = blockIdx.z;

    const uint32_t sbase = (uint32_t)__cvta_generic_to_shared(smf);

    const float* Qg = Q + ((size_t)(b * LT) + qt * 64) * DD + h * HD;
    const float* Kg = K + ((size_t)(b * HH + h)) * LS * HD;
    const float* Vg = V + ((size_t)(b * HH + h)) * LS * HD;
    const float* Bg = (MODE == 1) ? bias + ((size_t)h * LT + qt * 64) * LS : nullptr;

    {
        LOAD_TILE(0,     Qg, DD, 68);
        LOAD_TILE(4352,  Kg, HD, 68);
        LOAD_TILE(13056, Vg, HD, 72);
        if (MODE == 1) {
            LOAD_TILE(26624, Bg, LS, 68);
        }
        asm volatile("cp.async.commit_group;");
    }

    float oacc[8][4];
    #pragma unroll
    for (int ni = 0; ni < 8; ni++)
        #pragma unroll
        for (int r = 0; r < 4; r++) oacc[ni][r] = 0.0f;

    float mrow[2] = { -1e30f, -1e30f };
    float lrow[2] = { 0.0f, 0.0f };

    const int ktmax = (MODE == 0) ? qt : (LS / 64 - 1);

    for (int kt = 0; kt <= ktmax; kt++) {
        const int cur = kt & 1;
        __syncthreads();
        if (kt + 1 <= ktmax) {
            const int nk = kt + 1;
            const uint32_t koff = (cur == 0) ? 8704u  : 4352u;
            const uint32_t voff = (cur == 0) ? 17664u : 13056u;
            const float* kp = Kg + (size_t)nk * 64 * HD;
            const float* vp = Vg + (size_t)nk * 64 * HD;
            LOAD_TILE(koff, kp, HD, 68);
            LOAD_TILE(voff, vp, HD, 72);
            if (MODE == 1) {
                const uint32_t boff = (cur == 0) ? 30976u : 26624u;
                const float* bp = Bg + (size_t)nk * 64;
                LOAD_TILE(boff, bp, LS, 68);
            }
            asm volatile("cp.async.commit_group;");
            asm volatile("cp.async.wait_group 1;");
        } else {
            asm volatile("cp.async.wait_group 0;");
        }
        __syncthreads();

        const float* Ksc = smf + (cur ? 8704 : 4352);
        const float* Vsc = smf + (cur ? 17664 : 13056);
        const float* Bic = smf + (cur ? 30976 : 26624);

        // ---- S = Q K^T ----
        float sacc[8][4];
        #pragma unroll
        for (int ni = 0; ni < 8; ni++)
            #pragma unroll
            for (int r = 0; r < 4; r++) sacc[ni][r] = 0.0f;

        {
            const uint32_t* qb = (const uint32_t*)(smf + (wid * 16 + g) * 68 + t);
            const float* kb = Ksc + g * 68 + t;
            #pragma unroll
            for (int kk = 0; kk < 8; kk++) {
                uint32_t a[4];
                a[0] = qb[kk * 8];
                a[1] = qb[8 * 68 + kk * 8];
                a[2] = qb[kk * 8 + 4];
                a[3] = qb[8 * 68 + kk * 8 + 4];
                #pragma unroll
                for (int ni = 0; ni < 8; ni++) {
                    uint32_t bf[2];
                    bf[0] = f2tf32(kb[ni * 8 * 68 + kk * 8]);
                    bf[1] = f2tf32(kb[ni * 8 * 68 + kk * 8 + 4]);
                    mma_tf32(sacc[ni], a, bf);
                }
            }
        }

        // ---- softmax ----
        uint32_t* Psu = (uint32_t*)(smf + 22272);
        #pragma unroll
        for (int half = 0; half < 2; half++) {
            const int row_l = wid * 16 + g + half * 8;
            float mx = -1e30f;
            #pragma unroll
            for (int ni = 0; ni < 8; ni++) {
                #pragma unroll
                for (int c = 0; c < 2; c++) {
                    float v = sacc[ni][half * 2 + c] * 0.125f;
                    if (MODE == 0) {
                        if (kt == qt) {
                            int keyl = ni * 8 + 2 * t + c;
                            if (keyl > row_l) v = -1e30f;
                        }
                    } else {
                        v += Bic[row_l * 68 + ni * 8 + 2 * t + c];
                    }
                    sacc[ni][half * 2 + c] = v;
                    mx = fmaxf(mx, v);
                }
            }
            mx = fmaxf(mx, __shfl_xor_sync(0xffffffffu, mx, 1));
            mx = fmaxf(mx, __shfl_xor_sync(0xffffffffu, mx, 2));
            float mnew = fmaxf(mrow[half], mx);
            float corr = __expf(mrow[half] - mnew);
            mrow[half] = mnew;
            float sum = 0.0f;
            #pragma unroll
            for (int ni = 0; ni < 8; ni++) {
                float p0 = __expf(sacc[ni][half * 2]     - mnew);
                float p1 = __expf(sacc[ni][half * 2 + 1] - mnew);
                sum += p0 + p1;
                sacc[ni][half * 2]     = p0;
                sacc[ni][half * 2 + 1] = p1;
            }
            sum += __shfl_xor_sync(0xffffffffu, sum, 1);
            sum += __shfl_xor_sync(0xffffffffu, sum, 2);
            lrow[half] = lrow[half] * corr + sum;
            #pragma unroll
            for (int ni = 0; ni < 8; ni++) {
                oacc[ni][half * 2]     *= corr;
                oacc[ni][half * 2 + 1] *= corr;
                uint2 pp = make_uint2(f2tf32(sacc[ni][half * 2]),
                                      f2tf32(sacc[ni][half * 2 + 1]));
                *(uint2*)&Psu[row_l * 68 + ni * 8 + 2 * t] = pp;
            }
        }
        __syncwarp();

        // ---- O += P V ----
        {
            const uint32_t* pb = Psu + (wid * 16 + g) * 68 + t;
            const float* vb = Vsc + t * 72 + g;
            #pragma unroll
            for (int kk = 0; kk < 8; kk++) {
                uint32_t a[4];
                a[0] = pb[kk * 8];
                a[1] = pb[8 * 68 + kk * 8];
                a[2] = pb[kk * 8 + 4];
                a[3] = pb[8 * 68 + kk * 8 + 4];
                #pragma unroll
                for (int ni = 0; ni < 8; ni++) {
                    uint32_t bf[2];
                    bf[0] = f2tf32(vb[kk * 8 * 72 + ni * 8]);
                    bf[1] = f2tf32(vb[kk * 8 * 72 + 4 * 72 + ni * 8]);
                    mma_tf32(oacc[ni], a, bf);
                }
            }
        }
        __syncwarp();
    }

    // ---- normalize + write O (rounded: feeds GEMM A) ----
    #pragma unroll
    for (int half = 0; half < 2; half++) {
        const int row_l = wid * 16 + g + half * 8;
        const int qg = qt * 64 + row_l;
        const float invl = 1.0f / lrow[half];
        float* op = O + ((size_t)(b * LT) + qg) * DD + h * HD;
        #pragma unroll
        for (int ni = 0; ni < 8; ni++) {
            float2 v = make_float2(rtf(oacc[ni][half * 2] * invl),
                                   rtf(oacc[ni][half * 2 + 1] * invl));
            *(float2*)(op + ni * 8 + 2 * t) = v;
        }
    }
}

// ---------------------------------------------------------------------------
extern "C" void kernel_launch(void* const* d_in, const int* in_sizes, int n_in,
                              void* d_out, int out_size)
{
    const float* x        = (const float*)d_in[0];
    const float* memory   = (const float*)d_in[1];
    const float* pos_emb  = (const float*)d_in[2];
    const float* gamma_sa = (const float*)d_in[4];
    const float* wq_s     = (const float*)d_in[5];
    const float* wk_s     = (const float*)d_in[6];
    const float* wv_s     = (const float*)d_in[7];
    const float* wo_s     = (const float*)d_in[8];
    const float* gamma_ca = (const float*)d_in[9];
    const float* wq_c     = (const float*)d_in[10];
    const float* wk_c     = (const float*)d_in[11];
    const float* wv_c     = (const float*)d_in[12];
    const float* wo_c     = (const float*)d_in[13];
    const float* gamma_m  = (const float*)d_in[14];
    const float* w1       = (const float*)d_in[15];
    const float* w2       = (const float*)d_in[16];

    float* scratch = nullptr;
    cudaGetSymbolAddress((void**)&scratch, g_scratch);
    float* bh    = scratch;
    float* bq    = scratch + (size_t)1 * SLOT;
    float* battn = scratch + (size_t)2 * SLOT;
    float* bx1   = scratch + (size_t)3 * SLOT;
    float* bx2   = scratch + (size_t)4 * SLOT;
    float* bffn  = scratch + (size_t)5 * SLOT;
    float* wbase = scratch + WBASE;
    float* rwq_s = wbase + 0 * (size_t)WSZ;
    float* rwk_s = wbase + 1 * (size_t)WSZ;
    float* rwv_s = wbase + 2 * (size_t)WSZ;
    float* rwo_s = wbase + 3 * (size_t)WSZ;
    float* rwq_c = wbase + 4 * (size_t)WSZ;
    float* rwk_c = wbase + 5 * (size_t)WSZ;
    float* rwv_c = wbase + 6 * (size_t)WSZ;
    float* rwo_c = wbase + 7 * (size_t)WSZ;
    float* rw1   = wbase + 8 * (size_t)WSZ;    // 4*WSZ
    float* rw2   = wbase + 12 * (size_t)WSZ;   // 4*WSZ
    float* rmem  = wbase + 16 * (size_t)WSZ;   // 4*WSZ

    float* out   = (float*)d_out;
    float* o_mlp = out;
    float* o_ks  = out + (size_t)1 * SLOT;
    float* o_vs  = out + (size_t)2 * SLOT;
    float* o_kc  = out + (size_t)3 * SLOT;
    float* o_vc  = out + (size_t)4 * SLOT;

    cudaFuncSetAttribute(tc_gemm<1>, cudaFuncAttributeMaxDynamicSharedMemorySize, TC_SMEM_BYTES);
    cudaFuncSetAttribute(tc_gemm<2>, cudaFuncAttributeMaxDynamicSharedMemorySize, TC_SMEM_BYTES);
    cudaFuncSetAttribute(tc_gemm<3>, cudaFuncAttributeMaxDynamicSharedMemorySize, TC_SMEM_BYTES);
    cudaFuncSetAttribute(tc_gemm<4>, cudaFuncAttributeMaxDynamicSharedMemorySize, TC_SMEM_BYTES);
    cudaFuncSetAttribute(attn_tc<0>, cudaFuncAttributeMaxDynamicSharedMemorySize, ATT_SMEM0);
    cudaFuncSetAttribute(attn_tc<1>, cudaFuncAttributeMaxDynamicSharedMemorySize, ATT_SMEM1);

    // ---- tf32 rounding passes (weights + memory) ----
    #define RND(src, dst, nfloats) \
        round_tf32_kernel<<<(nfloats)/4/256, 256>>>((const float4*)(src), (float4*)(dst))
    RND(wq_s, rwq_s, WSZ); RND(wk_s, rwk_s, WSZ);
    RND(wv_s, rwv_s, WSZ); RND(wo_s, rwo_s, WSZ);
    RND(wq_c, rwq_c, WSZ); RND(wk_c, rwk_c, WSZ);
    RND(wv_c, rwv_c, WSZ); RND(wo_c, rwo_c, WSZ);
    RND(w1, rw1, 4*WSZ);   RND(w2, rw2, 4*WSZ);
    RND(memory, rmem, 4*WSZ);
    #undef RND

    const dim3 gD(DD / TC_BN, MTOT / TC_BM);   // (8, 32)
    const dim3 gF(FF / TC_BN, MTOT / TC_BM);   // (32, 32)
    const dim3 gA(LT / 64, HH, BB);

    // ---- self-attention block ----
    rmsnorm_kernel<<<MTOT, 256>>>(x, gamma_sa, bh);
    tc_gemm<4><<<gD, 256, TC_SMEM_BYTES>>>(bh, rwq_s, bq,   nullptr, MTOT, DD, DD);
    tc_gemm<1><<<gD, 256, TC_SMEM_BYTES>>>(bh, rwk_s, o_ks, nullptr, MTOT, DD, DD);
    tc_gemm<1><<<gD, 256, TC_SMEM_BYTES>>>(bh, rwv_s, o_vs, nullptr, MTOT, DD, DD);
    attn_tc<0><<<gA, 128, ATT_SMEM0>>>(bq, o_ks, o_vs, nullptr, battn);
    tc_gemm<2><<<gD, 256, TC_SMEM_BYTES>>>(battn, rwo_s, bx1, x, MTOT, DD, DD);

    // ---- cross-attention block ----
    rmsnorm_kernel<<<MTOT, 256>>>(bx1, gamma_ca, bh);
    tc_gemm<4><<<gD, 256, TC_SMEM_BYTES>>>(bh,   rwq_c, bq,   nullptr, MTOT, DD, DD);
    tc_gemm<1><<<gD, 256, TC_SMEM_BYTES>>>(rmem, rwk_c, o_kc, nullptr, MTOT, DD, DD);
    tc_gemm<1><<<gD, 256, TC_SMEM_BYTES>>>(rmem, rwv_c, o_vc, nullptr, MTOT, DD, DD);
    attn_tc<1><<<gA, 128, ATT_SMEM1>>>(bq, o_kc, o_vc, pos_emb, battn);
    tc_gemm<2><<<gD, 256, TC_SMEM_BYTES>>>(battn, rwo_c, bx2, bx1, MTOT, DD, DD);

    // ---- FFN block ----
    rmsnorm_kernel<<<MTOT, 256>>>(bx2, gamma_m, bh);
    tc_gemm<3><<<gF, 256, TC_SMEM_BYTES>>>(bh,   rw1, bffn,  nullptr, MTOT, FF, DD);
    tc_gemm<2><<<gD, 256, TC_SMEM_BYTES>>>(bffn, rw2, o_mlp, bx2,     MTOT, DD, FF);
}